// round 3
// baseline (speedup 1.0000x reference)
#include <cuda_runtime.h>
#include <math.h>

#define BB 4
#define SS 2048
#define DD 1024
#define HH 16
#define HDIM 64

// Scratch (device globals: allocation-free per harness rules)
__device__ float g_base[(size_t)BB * SS * 3 * DD];   // [8192, 3072]
__device__ float g_hidden[(size_t)BB * SS * DD];     // [8192, 1024]
__device__ float g_ctrl[(size_t)BB * SS * 5 * HH];   // [8192, 80]
__device__ float g_ys[(size_t)BB * SS * DD];         // [8192, 1024]
__device__ float g_mf[(size_t)BB * HH * HDIM * HDIM];// fallback M_final scratch

// ---------------------------------------------------------------------------
// Generic fp32 GEMM: C[M,N] = act(A[M,K] @ B[K,N] + bias[N])
// BM=128, BN=128, BK=8, 256 threads, 8x8 per thread.
// M, K assumed multiples of 128/8 (true here). N guarded (N=80 case).
// act: 0 = none, 1 = SiLU
// ---------------------------------------------------------------------------
#define BM 128
#define BN 128
#define BK 8

__global__ __launch_bounds__(256) void gemm_kernel(
    const float* __restrict__ A, const float* __restrict__ B,
    const float* __restrict__ bias, float* __restrict__ C,
    int M, int N, int K, int act)
{
    __shared__ __align__(16) float As[BK][BM];
    __shared__ __align__(16) float Bs[BK][BN];

    int tid = threadIdx.x;
    int bm = blockIdx.y * BM;
    int bn = blockIdx.x * BN;

    int a_r = tid >> 1;            // 0..127
    int a_c = (tid & 1) * 4;       // 0 or 4
    int b_r = tid >> 5;            // 0..7
    int b_c = (tid & 31) * 4;      // 0..124

    int tr = (tid >> 4) * 8;       // 0..120
    int tc = (tid & 15) * 8;       // 0..120

    float acc[8][8];
#pragma unroll
    for (int i = 0; i < 8; i++)
#pragma unroll
        for (int j = 0; j < 8; j++) acc[i][j] = 0.f;

    for (int k0 = 0; k0 < K; k0 += BK) {
        // Load A tile (transposed into As)
        float4 av = *(const float4*)&A[(size_t)(bm + a_r) * K + k0 + a_c];
        As[a_c + 0][a_r] = av.x;
        As[a_c + 1][a_r] = av.y;
        As[a_c + 2][a_r] = av.z;
        As[a_c + 3][a_r] = av.w;
        // Load B tile (N-guarded; N is a multiple of 4)
        float4 bv = make_float4(0.f, 0.f, 0.f, 0.f);
        if (bn + b_c < N)
            bv = *(const float4*)&B[(size_t)(k0 + b_r) * N + bn + b_c];
        *(float4*)&Bs[b_r][b_c] = bv;
        __syncthreads();

#pragma unroll
        for (int kk = 0; kk < BK; kk++) {
            float a[8], bb[8];
            *(float4*)&a[0]  = *(const float4*)&As[kk][tr];
            *(float4*)&a[4]  = *(const float4*)&As[kk][tr + 4];
            *(float4*)&bb[0] = *(const float4*)&Bs[kk][tc];
            *(float4*)&bb[4] = *(const float4*)&Bs[kk][tc + 4];
#pragma unroll
            for (int i = 0; i < 8; i++)
#pragma unroll
                for (int j = 0; j < 8; j++)
                    acc[i][j] += a[i] * bb[j];
        }
        __syncthreads();
    }

    // Epilogue
#pragma unroll
    for (int i = 0; i < 8; i++) {
        size_t row = (size_t)(bm + tr + i);
#pragma unroll
        for (int j = 0; j < 8; j++) {
            int col = bn + tc + j;
            if (col < N) {
                float v = acc[i][j] + bias[col];
                if (act == 1) v = v / (1.f + __expf(-v));  // SiLU
                C[row * N + col] = v;
            }
        }
    }
}

// ---------------------------------------------------------------------------
// Sequential scan. grid = 128 blocks: blockIdx.x = (b*16+h)*2 + half.
// Each block owns 32 rows of M[64,64] for one (b,h). 128 threads:
// thread = (row_in_half, colgroup) with 4 threads/row, 16 cols each (in regs).
// Rows of M are independent given shared (k,v,q,eta,alpha).
// ---------------------------------------------------------------------------
__global__ __launch_bounds__(128) void scan_kernel(
    const float* __restrict__ base,    // [B,S,H,3,HD] = [8192,3072]
    const float* __restrict__ ctrl,    // [B,S,H,5]    = [8192,80]
    const float* __restrict__ memory0, // [B,H,HD,HD]
    float* __restrict__ ys,            // [B,S,D]
    float* __restrict__ mfinal)        // [B,H,HD,HD]
{
    __shared__ __align__(16) float sk[64];
    __shared__ __align__(16) float sv[64];
    __shared__ __align__(16) float sq[64];

    int bh   = blockIdx.x >> 1;
    int half = blockIdx.x & 1;
    int b = bh >> 4, h = bh & 15;
    int tid = threadIdx.x;
    int r = (tid >> 2) + half * 32;  // row 0..63
    int g = tid & 3;                 // column group (16 cols)

    float m[16];
    {
        const float* M0 = memory0 + (((size_t)bh * HDIM + r) * HDIM + g * 16);
#pragma unroll
        for (int jj = 0; jj < 16; jj++) m[jj] = M0[jj];
    }

    const float* bptr = base + ((size_t)b * SS * HH + h) * 192;  // step stride 3072
    const float* cptr = ctrl + (size_t)b * SS * 80 + h * 5;      // step stride 80
    float* yptr = ys + (size_t)b * SS * DD + h * HDIM + r;

    // Prefetch step 0
    float pk = 0.f, pv = 0.f, pq = 0.f, pc0 = 0.f, pc1 = 0.f, pc2 = 0.f;
    float pc3, pc4;
    if (tid < 64) {
        pk = bptr[tid]; pv = bptr[64 + tid]; pq = bptr[128 + tid];
        pc0 = cptr[0]; pc1 = cptr[1]; pc2 = cptr[2];
    }
    pc3 = cptr[3]; pc4 = cptr[4];

    for (int s = 0; s < SS; s++) {
        __syncthreads();  // previous step's smem reads complete
        if (tid < 64) {
            sk[tid] = pk * pc0;
            sv[tid] = pv * pc1;
            sq[tid] = pq * pc2;
        }
        float eta   = 1.f / (1.f + __expf(-pc3));
        float alpha = 1.f / (1.f + __expf(-pc4));
        // Prefetch next step (hidden behind compute below)
        if (s + 1 < SS) {
            const float* bp = bptr + (size_t)(s + 1) * 3072;
            const float* cp = cptr + (size_t)(s + 1) * 80;
            if (tid < 64) {
                pk = bp[tid]; pv = bp[64 + tid]; pq = bp[128 + tid];
                pc0 = cp[0]; pc1 = cp[1]; pc2 = cp[2];
            }
            pc3 = cp[3]; pc4 = cp[4];
        }
        __syncthreads();  // smem k/v/q ready

        float kr[16], qr[16];
#pragma unroll
        for (int w = 0; w < 4; w++) {
            *(float4*)&kr[w * 4] = *(const float4*)&sk[g * 16 + w * 4];
            *(float4*)&qr[w * 4] = *(const float4*)&sq[g * 16 + w * 4];
        }
        float dq0 = 0.f, dq1 = 0.f, dk0 = 0.f, dk1 = 0.f;
#pragma unroll
        for (int jj = 0; jj < 16; jj += 2) {
            dq0 += m[jj] * qr[jj];
            dq1 += m[jj + 1] * qr[jj + 1];
            dk0 += m[jj] * kr[jj];
            dk1 += m[jj + 1] * kr[jj + 1];
        }
        float dq = dq0 + dq1, dk = dk0 + dk1;
        // Reduce across the 4-lane column groups (lanes 4r..4r+3)
        dq += __shfl_xor_sync(0xffffffffu, dq, 1);
        dq += __shfl_xor_sync(0xffffffffu, dq, 2);
        dk += __shfl_xor_sync(0xffffffffu, dk, 1);
        dk += __shfl_xor_sync(0xffffffffu, dk, 2);

        float err = dk - sv[r];
        if (g == 0) yptr[(size_t)s * DD] = dq;

        float ek = eta * err;
#pragma unroll
        for (int jj = 0; jj < 16; jj++)
            m[jj] = alpha * m[jj] + ek * kr[jj];
    }

    float* MF = mfinal + (((size_t)bh * HDIM + r) * HDIM + g * 16);
#pragma unroll
    for (int jj = 0; jj < 16; jj++) MF[jj] = m[jj];
}

// ---------------------------------------------------------------------------
extern "C" void kernel_launch(void* const* d_in, const int* in_sizes, int n_in,
                              void* d_out, int out_size)
{
    (void)in_sizes; (void)n_in;
    const float* x       = (const float*)d_in[0];
    const float* memory0 = (const float*)d_in[1];
    const float* W_in    = (const float*)d_in[2];
    const float* b_in    = (const float*)d_in[3];
    const float* Wc1     = (const float*)d_in[4];
    const float* bc1     = (const float*)d_in[5];
    const float* Wc2     = (const float*)d_in[6];
    const float* bc2     = (const float*)d_in[7];
    const float* W_out   = (const float*)d_in[8];
    const float* b_out   = (const float*)d_in[9];

    float* out = (float*)d_out;                          // [B,S,D] (+ maybe M_final)

    float *base, *hidden, *ctrl, *ys, *mf_scratch;
    cudaGetSymbolAddress((void**)&base,       g_base);
    cudaGetSymbolAddress((void**)&hidden,     g_hidden);
    cudaGetSymbolAddress((void**)&ctrl,       g_ctrl);
    cudaGetSymbolAddress((void**)&ys,         g_ys);
    cudaGetSymbolAddress((void**)&mf_scratch, g_mf);

    const size_t OUT_ELEMS = (size_t)BB * SS * DD;               // 8388608
    const size_t MF_ELEMS  = (size_t)BB * HH * HDIM * HDIM;      // 262144
    // Only write M_final into d_out if the harness actually sized it for
    // both outputs; otherwise keep it in scratch (avoids OOB on d_out).
    float* mfinal = ((size_t)out_size >= OUT_ELEMS + MF_ELEMS)
                        ? (out + OUT_ELEMS) : mf_scratch;

    const int Mrows = BB * SS;  // 8192

    // base = x @ W_in + b_in                  [8192,3072]
    gemm_kernel<<<dim3(3 * DD / BN, Mrows / BM), 256>>>(
        x, W_in, b_in, base, Mrows, 3 * DD, DD, 0);
    // hidden = silu(x @ Wc1 + bc1)            [8192,1024]
    gemm_kernel<<<dim3(DD / BN, Mrows / BM), 256>>>(
        x, Wc1, bc1, hidden, Mrows, DD, DD, 1);
    // ctrl = hidden @ Wc2 + bc2               [8192,80]
    gemm_kernel<<<dim3(1, Mrows / BM), 256>>>(
        hidden, Wc2, bc2, ctrl, Mrows, 5 * HH, DD, 0);
    // sequential scan                          ys [8192,1024], mfinal
    scan_kernel<<<BB * HH * 2, 128>>>(base, ctrl, memory0, ys, mfinal);
    // out = ys @ W_out + b_out                [8192,1024]
    gemm_kernel<<<dim3(DD / BN, Mrows / BM), 256>>>(
        ys, W_out, b_out, out, Mrows, DD, DD, 0);
}

// round 4
// speedup vs baseline: 1.8255x; 1.8255x over previous
#include <cuda_runtime.h>
#include <math.h>

#define BB 4
#define SS 2048
#define DD 1024
#define HH 16
#define HDIM 64

// Scratch (device globals: allocation-free per harness rules)
__device__ float g_base[(size_t)BB * SS * 3 * DD];   // [8192, 3072]
__device__ float g_hidden[(size_t)BB * SS * DD];     // [8192, 1024]
__device__ float g_ctrl[(size_t)BB * SS * 5 * HH];   // [8192, 80]
__device__ float g_ys[(size_t)BB * SS * DD];         // [8192, 1024]
__device__ float g_mf[(size_t)BB * HH * HDIM * HDIM];// fallback M_final scratch

// ---------------------------------------------------------------------------
// tf32 tensor-core GEMM: C[M,N] = act(A[M,K] @ B[K,N] + bias[N])
// 128x128x16 tile, 256 threads (8 warps, warp tile 32x64), mma.m16n8k8.tf32,
// double-buffered smem with register staging.
// As layout [m][k] stride 20 (conflict-free frags), Bs [k][n] stride 136.
// act: 0 = none, 1 = SiLU. M,K multiples of 128/16; N guarded (N=80 case).
// ---------------------------------------------------------------------------
#define TBM 128
#define TBN 128
#define TBK 16
#define ASTR 20
#define BSTR 136

__device__ __forceinline__ unsigned f2tf32(float f) {
    unsigned r;
    asm("cvt.rna.tf32.f32 %0, %1;" : "=r"(r) : "f"(f));
    return r;
}

__device__ __forceinline__ void mma_tf32(float* c, const unsigned* a,
                                         unsigned b0, unsigned b1) {
    asm volatile(
        "mma.sync.aligned.m16n8k8.row.col.f32.tf32.tf32.f32 "
        "{%0,%1,%2,%3}, {%4,%5,%6,%7}, {%8,%9}, {%0,%1,%2,%3};"
        : "+f"(c[0]), "+f"(c[1]), "+f"(c[2]), "+f"(c[3])
        : "r"(a[0]), "r"(a[1]), "r"(a[2]), "r"(a[3]), "r"(b0), "r"(b1));
}

__global__ __launch_bounds__(256) void gemm_tf32(
    const float* __restrict__ A, const float* __restrict__ B,
    const float* __restrict__ bias, float* __restrict__ C,
    int M, int N, int K, int act)
{
    __shared__ __align__(16) unsigned As[2][TBM * ASTR];
    __shared__ __align__(16) unsigned Bs[2][TBK * BSTR];

    int tid  = threadIdx.x;
    int lane = tid & 31;
    int warp = tid >> 5;
    int wm = warp >> 1;          // 0..3 -> M offset wm*32
    int wn = warp & 1;           // 0..1 -> N offset wn*64
    int bm = blockIdx.y * TBM;
    int bn = blockIdx.x * TBN;

    // global->smem load mapping
    int ar = tid >> 2;           // A rows 0..63 (and +64)
    int aq = (tid & 3) * 4;      // A k offset (float4)
    int br = tid >> 4;           // B row 0..15
    int bc = (tid & 15) * 4;     // B col (float4), and +64

    const float* Ap0 = A + (size_t)(bm + ar) * K + aq;
    const float* Ap1 = A + (size_t)(bm + ar + 64) * K + aq;
    int bcol0 = bn + bc, bcol1 = bn + bc + 64;

    float acc[2][8][4];
#pragma unroll
    for (int i = 0; i < 2; i++)
#pragma unroll
        for (int j = 0; j < 8; j++)
#pragma unroll
            for (int l = 0; l < 4; l++) acc[i][j][l] = 0.f;

    const float4 z4 = make_float4(0.f, 0.f, 0.f, 0.f);

    // prologue: tile 0 -> buf 0
    {
        float4 va0 = *(const float4*)Ap0;
        float4 va1 = *(const float4*)Ap1;
        const float* Brow = B + (size_t)br * N;
        float4 vb0 = (bcol0 < N) ? *(const float4*)&Brow[bcol0] : z4;
        float4 vb1 = (bcol1 < N) ? *(const float4*)&Brow[bcol1] : z4;
        uint4 u;
        u.x = f2tf32(va0.x); u.y = f2tf32(va0.y); u.z = f2tf32(va0.z); u.w = f2tf32(va0.w);
        *(uint4*)&As[0][ar * ASTR + aq] = u;
        u.x = f2tf32(va1.x); u.y = f2tf32(va1.y); u.z = f2tf32(va1.z); u.w = f2tf32(va1.w);
        *(uint4*)&As[0][(ar + 64) * ASTR + aq] = u;
        u.x = f2tf32(vb0.x); u.y = f2tf32(vb0.y); u.z = f2tf32(vb0.z); u.w = f2tf32(vb0.w);
        *(uint4*)&Bs[0][br * BSTR + bc] = u;
        u.x = f2tf32(vb1.x); u.y = f2tf32(vb1.y); u.z = f2tf32(vb1.z); u.w = f2tf32(vb1.w);
        *(uint4*)&Bs[0][br * BSTR + bc + 64] = u;
    }
    __syncthreads();

    int iters = K / TBK;
    for (int it = 1; it <= iters; it++) {
        float4 va0, va1, vb0, vb1;
        bool has = (it < iters);
        if (has) {
            int k0 = it * TBK;
            va0 = *(const float4*)(Ap0 + k0);
            va1 = *(const float4*)(Ap1 + k0);
            const float* Brow = B + (size_t)(k0 + br) * N;
            vb0 = (bcol0 < N) ? *(const float4*)&Brow[bcol0] : z4;
            vb1 = (bcol1 < N) ? *(const float4*)&Brow[bcol1] : z4;
        }

        // compute on buffer (it-1)&1
        {
            int buf = (it - 1) & 1;
            const unsigned* Asb = As[buf];
            const unsigned* Bsb = Bs[buf];
#pragma unroll
            for (int kc = 0; kc < TBK; kc += 8) {
                unsigned afr[2][4];
                int arow = wm * 32 + (lane >> 2);
                int ak = kc + (lane & 3);
#pragma unroll
                for (int i = 0; i < 2; i++) {
                    const unsigned* p = &Asb[(arow + i * 16) * ASTR];
                    afr[i][0] = p[ak];
                    afr[i][1] = p[8 * ASTR + ak];
                    afr[i][2] = p[ak + 4];
                    afr[i][3] = p[8 * ASTR + ak + 4];
                }
                int bk = kc + (lane & 3);
                int bcl = wn * 64 + (lane >> 2);
                const unsigned* pb0 = &Bsb[bk * BSTR + bcl];
                const unsigned* pb1 = &Bsb[(bk + 4) * BSTR + bcl];
#pragma unroll
                for (int j = 0; j < 8; j++) {
                    unsigned b0 = pb0[j * 8];
                    unsigned b1 = pb1[j * 8];
                    mma_tf32(acc[0][j], afr[0], b0, b1);
                    mma_tf32(acc[1][j], afr[1], b0, b1);
                }
            }
        }

        if (has) {
            int buf = it & 1;
            uint4 u;
            u.x = f2tf32(va0.x); u.y = f2tf32(va0.y); u.z = f2tf32(va0.z); u.w = f2tf32(va0.w);
            *(uint4*)&As[buf][ar * ASTR + aq] = u;
            u.x = f2tf32(va1.x); u.y = f2tf32(va1.y); u.z = f2tf32(va1.z); u.w = f2tf32(va1.w);
            *(uint4*)&As[buf][(ar + 64) * ASTR + aq] = u;
            u.x = f2tf32(vb0.x); u.y = f2tf32(vb0.y); u.z = f2tf32(vb0.z); u.w = f2tf32(vb0.w);
            *(uint4*)&Bs[buf][br * BSTR + bc] = u;
            u.x = f2tf32(vb1.x); u.y = f2tf32(vb1.y); u.z = f2tf32(vb1.z); u.w = f2tf32(vb1.w);
            *(uint4*)&Bs[buf][br * BSTR + bc + 64] = u;
        }
        __syncthreads();
    }

    // epilogue: c0,c1 at (row, col0..col0+1), c2,c3 at (row+8, ...)
#pragma unroll
    for (int i = 0; i < 2; i++) {
        int row = bm + wm * 32 + i * 16 + (lane >> 2);
#pragma unroll
        for (int j = 0; j < 8; j++) {
            int col = bn + wn * 64 + j * 8 + (lane & 3) * 2;
            if (col < N) {
                float b0 = bias[col], b1 = bias[col + 1];
                float v0 = acc[i][j][0] + b0;
                float v1 = acc[i][j][1] + b1;
                float v2 = acc[i][j][2] + b0;
                float v3 = acc[i][j][3] + b1;
                if (act == 1) {
                    v0 = v0 / (1.f + __expf(-v0));
                    v1 = v1 / (1.f + __expf(-v1));
                    v2 = v2 / (1.f + __expf(-v2));
                    v3 = v3 / (1.f + __expf(-v3));
                }
                *(float2*)&C[(size_t)row * N + col] = make_float2(v0, v1);
                *(float2*)&C[(size_t)(row + 8) * N + col] = make_float2(v2, v3);
            }
        }
    }
}

// ---------------------------------------------------------------------------
// Sequential scan. grid = 128 blocks: blockIdx.x = (b*16+h)*2 + half.
// Each block owns 32 rows of M[64,64] for one (b,h). 128 threads:
// thread = (row_in_half, colgroup) with 4 threads/row, 16 cols each (in regs).
// ---------------------------------------------------------------------------
__global__ __launch_bounds__(128) void scan_kernel(
    const float* __restrict__ base,    // [B,S,H,3,HD] = [8192,3072]
    const float* __restrict__ ctrl,    // [B,S,H,5]    = [8192,80]
    const float* __restrict__ memory0, // [B,H,HD,HD]
    float* __restrict__ ys,            // [B,S,D]
    float* __restrict__ mfinal)        // [B,H,HD,HD]
{
    __shared__ __align__(16) float sk[64];
    __shared__ __align__(16) float sv[64];
    __shared__ __align__(16) float sq[64];

    int bh   = blockIdx.x >> 1;
    int half = blockIdx.x & 1;
    int b = bh >> 4, h = bh & 15;
    int tid = threadIdx.x;
    int r = (tid >> 2) + half * 32;  // row 0..63
    int g = tid & 3;                 // column group (16 cols)

    float m[16];
    {
        const float* M0 = memory0 + (((size_t)bh * HDIM + r) * HDIM + g * 16);
#pragma unroll
        for (int jj = 0; jj < 16; jj++) m[jj] = M0[jj];
    }

    const float* bptr = base + ((size_t)b * SS * HH + h) * 192;  // step stride 3072
    const float* cptr = ctrl + (size_t)b * SS * 80 + h * 5;      // step stride 80
    float* yptr = ys + (size_t)b * SS * DD + h * HDIM + r;

    // Prefetch step 0
    float pk = 0.f, pv = 0.f, pq = 0.f, pc0 = 0.f, pc1 = 0.f, pc2 = 0.f;
    float pc3, pc4;
    if (tid < 64) {
        pk = bptr[tid]; pv = bptr[64 + tid]; pq = bptr[128 + tid];
        pc0 = cptr[0]; pc1 = cptr[1]; pc2 = cptr[2];
    }
    pc3 = cptr[3]; pc4 = cptr[4];

    for (int s = 0; s < SS; s++) {
        __syncthreads();
        if (tid < 64) {
            sk[tid] = pk * pc0;
            sv[tid] = pv * pc1;
            sq[tid] = pq * pc2;
        }
        float eta   = 1.f / (1.f + __expf(-pc3));
        float alpha = 1.f / (1.f + __expf(-pc4));
        if (s + 1 < SS) {
            const float* bp = bptr + (size_t)(s + 1) * 3072;
            const float* cp = cptr + (size_t)(s + 1) * 80;
            if (tid < 64) {
                pk = bp[tid]; pv = bp[64 + tid]; pq = bp[128 + tid];
                pc0 = cp[0]; pc1 = cp[1]; pc2 = cp[2];
            }
            pc3 = cp[3]; pc4 = cp[4];
        }
        __syncthreads();

        float kr[16], qr[16];
#pragma unroll
        for (int w = 0; w < 4; w++) {
            *(float4*)&kr[w * 4] = *(const float4*)&sk[g * 16 + w * 4];
            *(float4*)&qr[w * 4] = *(const float4*)&sq[g * 16 + w * 4];
        }
        float dq0 = 0.f, dq1 = 0.f, dk0 = 0.f, dk1 = 0.f;
#pragma unroll
        for (int jj = 0; jj < 16; jj += 2) {
            dq0 += m[jj] * qr[jj];
            dq1 += m[jj + 1] * qr[jj + 1];
            dk0 += m[jj] * kr[jj];
            dk1 += m[jj + 1] * kr[jj + 1];
        }
        float dq = dq0 + dq1, dk = dk0 + dk1;
        dq += __shfl_xor_sync(0xffffffffu, dq, 1);
        dq += __shfl_xor_sync(0xffffffffu, dq, 2);
        dk += __shfl_xor_sync(0xffffffffu, dk, 1);
        dk += __shfl_xor_sync(0xffffffffu, dk, 2);

        float err = dk - sv[r];
        if (g == 0) yptr[(size_t)s * DD] = dq;

        float ek = eta * err;
#pragma unroll
        for (int jj = 0; jj < 16; jj++)
            m[jj] = alpha * m[jj] + ek * kr[jj];
    }

    float* MF = mfinal + (((size_t)bh * HDIM + r) * HDIM + g * 16);
#pragma unroll
    for (int jj = 0; jj < 16; jj++) MF[jj] = m[jj];
}

// ---------------------------------------------------------------------------
extern "C" void kernel_launch(void* const* d_in, const int* in_sizes, int n_in,
                              void* d_out, int out_size)
{
    (void)in_sizes; (void)n_in;
    const float* x       = (const float*)d_in[0];
    const float* memory0 = (const float*)d_in[1];
    const float* W_in    = (const float*)d_in[2];
    const float* b_in    = (const float*)d_in[3];
    const float* Wc1     = (const float*)d_in[4];
    const float* bc1     = (const float*)d_in[5];
    const float* Wc2     = (const float*)d_in[6];
    const float* bc2     = (const float*)d_in[7];
    const float* W_out   = (const float*)d_in[8];
    const float* b_out   = (const float*)d_in[9];

    float* out = (float*)d_out;

    float *base, *hidden, *ctrl, *ys, *mf_scratch;
    cudaGetSymbolAddress((void**)&base,       g_base);
    cudaGetSymbolAddress((void**)&hidden,     g_hidden);
    cudaGetSymbolAddress((void**)&ctrl,       g_ctrl);
    cudaGetSymbolAddress((void**)&ys,         g_ys);
    cudaGetSymbolAddress((void**)&mf_scratch, g_mf);

    const size_t OUT_ELEMS = (size_t)BB * SS * DD;               // 8388608
    const size_t MF_ELEMS  = (size_t)BB * HH * HDIM * HDIM;      // 262144
    float* mfinal = ((size_t)out_size >= OUT_ELEMS + MF_ELEMS)
                        ? (out + OUT_ELEMS) : mf_scratch;

    const int Mrows = BB * SS;  // 8192

    // base = x @ W_in + b_in                  [8192,3072]
    gemm_tf32<<<dim3(3 * DD / TBN, Mrows / TBM), 256>>>(
        x, W_in, b_in, base, Mrows, 3 * DD, DD, 0);
    // hidden = silu(x @ Wc1 + bc1)            [8192,1024]
    gemm_tf32<<<dim3(DD / TBN, Mrows / TBM), 256>>>(
        x, Wc1, bc1, hidden, Mrows, DD, DD, 1);
    // ctrl = hidden @ Wc2 + bc2               [8192,80]
    gemm_tf32<<<dim3(1, Mrows / TBM), 256>>>(
        hidden, Wc2, bc2, ctrl, Mrows, 5 * HH, DD, 0);
    // sequential scan                          ys [8192,1024], mfinal
    scan_kernel<<<BB * HH * 2, 128>>>(base, ctrl, memory0, ys, mfinal);
    // out = ys @ W_out + b_out                [8192,1024]
    gemm_tf32<<<dim3(DD / TBN, Mrows / TBM), 256>>>(
        ys, W_out, b_out, out, Mrows, DD, DD, 0);
}